// round 1
// baseline (speedup 1.0000x reference)
#include <cuda_runtime.h>
#include <math.h>

#define NTOK 8192
#define CDIM 1024
#define HDIM 4096
#define NEXP 8
#define NSLOT (2*NTOK)

// ---------------- device scratch (static, allocation-free) ----------------
__device__ int   g_counts[NEXP];
__device__ int   g_offsets[NEXP];
__device__ int   g_tokens[NEXP * NTOK];      // token index per (expert, pos)
__device__ float g_slot_gate[NEXP * NTOK];   // gate per (expert, pos)
__device__ float g_h[(size_t)NSLOT * HDIM];  // gelu(x @ w1^T) rows, grouped by expert

// ---------------- helpers ----------------
__device__ __forceinline__ float new_gelu(float v) {
    const float c = 0.7978845608028654f; // sqrt(2/pi)
    float u = c * (v + 0.044715f * v * v * v);
    return 0.5f * v * (1.0f + tanhf(u));
}

// ---------------- kernel 0: reset counters ----------------
__global__ void init_kernel() {
    if (threadIdx.x < NEXP) g_counts[threadIdx.x] = 0;
}

// ---------------- kernel 1: router (one warp per token) ----------------
__global__ void router_kernel(const float* __restrict__ x,
                              const float* __restrict__ rw) {
    int warp = (blockIdx.x * blockDim.x + threadIdx.x) >> 5;
    int lane = threadIdx.x & 31;
    if (warp >= NTOK) return;
    const float* xr = x + (size_t)warp * CDIM;

    float acc[NEXP];
#pragma unroll
    for (int e = 0; e < NEXP; e++) acc[e] = 0.f;

    for (int c = lane; c < CDIM; c += 32) {
        float xv = xr[c];
#pragma unroll
        for (int e = 0; e < NEXP; e++)
            acc[e] = fmaf(xv, rw[e * CDIM + c], acc[e]);
    }
#pragma unroll
    for (int off = 16; off > 0; off >>= 1)
#pragma unroll
        for (int e = 0; e < NEXP; e++)
            acc[e] += __shfl_xor_sync(0xffffffffu, acc[e], off);

    if (lane == 0) {
        float mx = acc[0];
#pragma unroll
        for (int e = 1; e < NEXP; e++) mx = fmaxf(mx, acc[e]);
        float p[NEXP];
        float s = 0.f;
#pragma unroll
        for (int e = 0; e < NEXP; e++) { p[e] = expf(acc[e] - mx); s += p[e]; }
        float inv = 1.f / s;
#pragma unroll
        for (int e = 0; e < NEXP; e++) p[e] *= inv;

        // top-2 (ties -> lower index, matching jax.lax.top_k)
        int i0 = 0;
#pragma unroll
        for (int e = 1; e < NEXP; e++) if (p[e] > p[i0]) i0 = e;
        int i1 = (i0 == 0) ? 1 : 0;
#pragma unroll
        for (int e = 0; e < NEXP; e++)
            if (e != i0 && p[e] > p[i1]) i1 = e;

        float denom = p[i0] + p[i1] + 1e-8f;
        float g0 = p[i0] / denom;
        float g1 = p[i1] / denom;

        int pos0 = atomicAdd(&g_counts[i0], 1);
        g_tokens[i0 * NTOK + pos0]    = warp;
        g_slot_gate[i0 * NTOK + pos0] = g0;
        int pos1 = atomicAdd(&g_counts[i1], 1);
        g_tokens[i1 * NTOK + pos1]    = warp;
        g_slot_gate[i1 * NTOK + pos1] = g1;
    }
}

// ---------------- kernel 2: exclusive prefix of counts ----------------
__global__ void offsets_kernel() {
    if (threadIdx.x == 0) {
        int s = 0;
        for (int e = 0; e < NEXP; e++) { g_offsets[e] = s; s += g_counts[e]; }
    }
}

// ---------------- GEMM 1: h = gelu(x[tokens] @ w1[e]^T + b1[e]) ----------
// A: gathered x rows [cnt, CDIM] ; B: w1[e] [HDIM, CDIM] (both K-major)
// tile 128x128x16, 256 threads, 8x8 per thread.
#define SMS 132  // padded smem row stride (float4-aligned, conflict-reducing)

__global__ void __launch_bounds__(256, 2)
gemm1_kernel(const float* __restrict__ x,
             const float* __restrict__ w1,
             const float* __restrict__ b1) {
    const int e   = blockIdx.z;
    const int cnt = g_counts[e];
    const int m0  = blockIdx.y * 128;
    if (m0 >= cnt) return;
    const int n0  = blockIdx.x * 128;
    const int off = g_offsets[e];

    __shared__ float As[16][SMS];
    __shared__ float Bs[16][SMS];

    const int tid = threadIdx.x;
    const int tx = tid & 15;   // N direction
    const int ty = tid >> 4;   // M direction

    // Loader mapping: two float4 per thread per operand per k-tile.
    // l = tid + j*256 ; row = l>>2 ; k = (l&3)*4
    const float* aBase[2];
#pragma unroll
    for (int j = 0; j < 2; j++) {
        int l  = tid + j * 256;
        int r  = l >> 2;
        int gm = m0 + r;
        aBase[j] = (gm < cnt) ? (x + (size_t)g_tokens[e * NTOK + gm] * CDIM)
                              : (const float*)0;
    }
    const float* w1e = w1 + (size_t)e * HDIM * CDIM;

    float acc[8][8];
#pragma unroll
    for (int i = 0; i < 8; i++)
#pragma unroll
        for (int j = 0; j < 8; j++) acc[i][j] = 0.f;

    for (int kt = 0; kt < CDIM; kt += 16) {
#pragma unroll
        for (int j = 0; j < 2; j++) {
            int l = tid + j * 256;
            int r = l >> 2;
            int k = (l & 3) * 4;
            float4 va = aBase[j] ? *(const float4*)(aBase[j] + kt + k)
                                 : make_float4(0.f, 0.f, 0.f, 0.f);
            As[k + 0][r] = va.x; As[k + 1][r] = va.y;
            As[k + 2][r] = va.z; As[k + 3][r] = va.w;
            float4 vb = *(const float4*)(w1e + (size_t)(n0 + r) * CDIM + kt + k);
            Bs[k + 0][r] = vb.x; Bs[k + 1][r] = vb.y;
            Bs[k + 2][r] = vb.z; Bs[k + 3][r] = vb.w;
        }
        __syncthreads();
#pragma unroll
        for (int kk = 0; kk < 16; kk++) {
            float a[8], b[8];
            *(float4*)&a[0] = *(const float4*)&As[kk][ty * 8];
            *(float4*)&a[4] = *(const float4*)&As[kk][ty * 8 + 4];
            *(float4*)&b[0] = *(const float4*)&Bs[kk][tx * 8];
            *(float4*)&b[4] = *(const float4*)&Bs[kk][tx * 8 + 4];
#pragma unroll
            for (int i = 0; i < 8; i++)
#pragma unroll
                for (int j = 0; j < 8; j++)
                    acc[i][j] = fmaf(a[i], b[j], acc[i][j]);
        }
        __syncthreads();
    }

    // epilogue: bias + gelu -> g_h
#pragma unroll
    for (int i = 0; i < 8; i++) {
        int gm = m0 + ty * 8 + i;
        if (gm >= cnt) break;
        float* hrow = g_h + (size_t)(off + gm) * HDIM + n0 + tx * 8;
#pragma unroll
        for (int j = 0; j < 8; j++) {
            float v = acc[i][j] + b1[e * HDIM + n0 + tx * 8 + j];
            hrow[j] = new_gelu(v);
        }
    }
}

// ---------------- GEMM 2: out += gate * (h @ w2[e]^T + b2[e]) ------------
// A: g_h rows [cnt, HDIM] contiguous at offset ; B: w2[e] [CDIM, HDIM]
__global__ void __launch_bounds__(256, 2)
gemm2_kernel(const float* __restrict__ w2,
             const float* __restrict__ b2,
             float* __restrict__ out) {
    const int e   = blockIdx.z;
    const int cnt = g_counts[e];
    const int m0  = blockIdx.y * 128;
    if (m0 >= cnt) return;
    const int n0  = blockIdx.x * 128;
    const int off = g_offsets[e];

    __shared__ float As[16][SMS];
    __shared__ float Bs[16][SMS];

    const int tid = threadIdx.x;
    const int tx = tid & 15;
    const int ty = tid >> 4;

    const float* aBase[2];
#pragma unroll
    for (int j = 0; j < 2; j++) {
        int l  = tid + j * 256;
        int r  = l >> 2;
        int gm = m0 + r;
        aBase[j] = (gm < cnt) ? (g_h + (size_t)(off + gm) * HDIM)
                              : (const float*)0;
    }
    const float* w2e = w2 + (size_t)e * CDIM * HDIM;

    float acc[8][8];
#pragma unroll
    for (int i = 0; i < 8; i++)
#pragma unroll
        for (int j = 0; j < 8; j++) acc[i][j] = 0.f;

    for (int kt = 0; kt < HDIM; kt += 16) {
#pragma unroll
        for (int j = 0; j < 2; j++) {
            int l = tid + j * 256;
            int r = l >> 2;
            int k = (l & 3) * 4;
            float4 va = aBase[j] ? *(const float4*)(aBase[j] + kt + k)
                                 : make_float4(0.f, 0.f, 0.f, 0.f);
            As[k + 0][r] = va.x; As[k + 1][r] = va.y;
            As[k + 2][r] = va.z; As[k + 3][r] = va.w;
            float4 vb = *(const float4*)(w2e + (size_t)(n0 + r) * HDIM + kt + k);
            Bs[k + 0][r] = vb.x; Bs[k + 1][r] = vb.y;
            Bs[k + 2][r] = vb.z; Bs[k + 3][r] = vb.w;
        }
        __syncthreads();
#pragma unroll
        for (int kk = 0; kk < 16; kk++) {
            float a[8], b[8];
            *(float4*)&a[0] = *(const float4*)&As[kk][ty * 8];
            *(float4*)&a[4] = *(const float4*)&As[kk][ty * 8 + 4];
            *(float4*)&b[0] = *(const float4*)&Bs[kk][tx * 8];
            *(float4*)&b[4] = *(const float4*)&Bs[kk][tx * 8 + 4];
#pragma unroll
            for (int i = 0; i < 8; i++)
#pragma unroll
                for (int j = 0; j < 8; j++)
                    acc[i][j] = fmaf(a[i], b[j], acc[i][j]);
        }
        __syncthreads();
    }

    // epilogue: gated scatter-add into output
#pragma unroll
    for (int i = 0; i < 8; i++) {
        int gm = m0 + ty * 8 + i;
        if (gm >= cnt) break;
        int   token = g_tokens[e * NTOK + gm];
        float gate  = g_slot_gate[e * NTOK + gm];
        float* orow = out + (size_t)token * CDIM;
#pragma unroll
        for (int j = 0; j < 8; j++) {
            int col = n0 + tx * 8 + j;
            float v = acc[i][j] + b2[e * CDIM + col];
            atomicAdd(&orow[col], gate * v);
        }
    }
}

// ---------------- launch ----------------
extern "C" void kernel_launch(void* const* d_in, const int* in_sizes, int n_in,
                              void* d_out, int out_size) {
    const float* x  = (const float*)d_in[0];
    const float* rw = (const float*)d_in[1];
    const float* w1 = (const float*)d_in[2];
    const float* b1 = (const float*)d_in[3];
    const float* w2 = (const float*)d_in[4];
    const float* b2 = (const float*)d_in[5];
    float* out = (float*)d_out;

    cudaMemsetAsync(out, 0, (size_t)out_size * sizeof(float), 0);
    init_kernel<<<1, 32>>>();
    router_kernel<<<(NTOK * 32 + 255) / 256, 256>>>(x, rw);
    offsets_kernel<<<1, 32>>>();

    dim3 g1(HDIM / 128, NTOK / 128, NEXP);
    gemm1_kernel<<<g1, 256>>>(x, w1, b1);

    dim3 g2(CDIM / 128, NTOK / 128, NEXP);
    gemm2_kernel<<<g2, 256>>>(w2, b2, out);
}

// round 2
// speedup vs baseline: 2.6340x; 2.6340x over previous
#include <cuda_runtime.h>
#include <math.h>

#define NTOK 8192
#define CDIM 1024
#define HDIM 4096
#define NEXP 8
#define NSLOT (2*NTOK)

// ---------------- device scratch (static, allocation-free) ----------------
__device__ int   g_counts[NEXP];
__device__ int   g_offsets[NEXP];
__device__ int   g_tokens[NEXP * NTOK];
__device__ float g_gate[NEXP * NTOK];
__device__ float g_h[(size_t)NSLOT * HDIM];   // tf32-rounded activations

// ---------------- helpers ----------------
__device__ __forceinline__ float new_gelu(float v) {
    const float c = 0.7978845608028654f;
    float u = c * (v + 0.044715f * v * v * v);
    return 0.5f * v * (1.0f + tanhf(u));
}
__device__ __forceinline__ unsigned f2tf(float f) {
    unsigned u;
    asm("cvt.rna.tf32.f32 %0, %1;" : "=r"(u) : "f"(f));
    return u;
}
__device__ __forceinline__ void mma_tf32(float* c, const unsigned* a, const unsigned* b) {
    asm volatile(
        "mma.sync.aligned.m16n8k8.row.col.f32.tf32.tf32.f32 "
        "{%0,%1,%2,%3}, {%4,%5,%6,%7}, {%8,%9}, {%0,%1,%2,%3};"
        : "+f"(c[0]), "+f"(c[1]), "+f"(c[2]), "+f"(c[3])
        : "r"(a[0]), "r"(a[1]), "r"(a[2]), "r"(a[3]), "r"(b[0]), "r"(b[1]));
}
// swizzled smem index: row-major [128][32] floats, col4 XORed with row&7
__device__ __forceinline__ int swz(int row, int k4) {
    return row * 32 + ((k4 ^ (row & 7)) << 2);
}

// ---------------- kernel 0: reset counters ----------------
__global__ void init_kernel() {
    if (threadIdx.x < NEXP) g_counts[threadIdx.x] = 0;
}

// ---------------- kernel 1: router (one warp per token) ----------------
__global__ void router_kernel(const float* __restrict__ x,
                              const float* __restrict__ rw) {
    int warp = (blockIdx.x * blockDim.x + threadIdx.x) >> 5;
    int lane = threadIdx.x & 31;
    if (warp >= NTOK) return;
    const float* xr = x + (size_t)warp * CDIM;

    float acc[NEXP];
#pragma unroll
    for (int e = 0; e < NEXP; e++) acc[e] = 0.f;
    for (int c = lane; c < CDIM; c += 32) {
        float xv = xr[c];
#pragma unroll
        for (int e = 0; e < NEXP; e++)
            acc[e] = fmaf(xv, rw[e * CDIM + c], acc[e]);
    }
#pragma unroll
    for (int off = 16; off > 0; off >>= 1)
#pragma unroll
        for (int e = 0; e < NEXP; e++)
            acc[e] += __shfl_xor_sync(0xffffffffu, acc[e], off);

    if (lane == 0) {
        float mx = acc[0];
#pragma unroll
        for (int e = 1; e < NEXP; e++) mx = fmaxf(mx, acc[e]);
        float p[NEXP], s = 0.f;
#pragma unroll
        for (int e = 0; e < NEXP; e++) { p[e] = expf(acc[e] - mx); s += p[e]; }
        float inv = 1.f / s;
#pragma unroll
        for (int e = 0; e < NEXP; e++) p[e] *= inv;

        int i0 = 0;
#pragma unroll
        for (int e = 1; e < NEXP; e++) if (p[e] > p[i0]) i0 = e;
        int i1 = (i0 == 0) ? 1 : 0;
#pragma unroll
        for (int e = 0; e < NEXP; e++)
            if (e != i0 && p[e] > p[i1]) i1 = e;

        float denom = p[i0] + p[i1] + 1e-8f;
        int pos0 = atomicAdd(&g_counts[i0], 1);
        g_tokens[i0 * NTOK + pos0] = warp;
        g_gate[i0 * NTOK + pos0]   = p[i0] / denom;
        int pos1 = atomicAdd(&g_counts[i1], 1);
        g_tokens[i1 * NTOK + pos1] = warp;
        g_gate[i1 * NTOK + pos1]   = p[i1] / denom;
    }
}

// ---------------- kernel 2: exclusive prefix ----------------
__global__ void offsets_kernel() {
    if (threadIdx.x == 0) {
        int s = 0;
        for (int e = 0; e < NEXP; e++) { g_offsets[e] = s; s += g_counts[e]; }
    }
}

// =====================================================================
// TF32 tensor-core GEMMs: BM=128 BN=128 BK=32, 8 warps, warp tile 64x32
// A: [rows, K] K-major (gathered); B: [cols, K] K-major; C = A @ B^T
// =====================================================================

struct Frag { float acc[4][4][4]; };

__device__ __forceinline__ void gemm_core(
    const float* const* aRow, const float* const* bRow, int Kdim,
    unsigned* As, unsigned* Bs, Frag& f)
{
    const int tid  = threadIdx.x;
    const int lane = tid & 31;
    const int wid  = tid >> 5;
    const int wm   = (wid & 1) * 64;
    const int wn   = (wid >> 1) * 32;
    const int g    = lane >> 2;
    const int t    = lane & 3;

#pragma unroll
    for (int mi = 0; mi < 4; mi++)
#pragma unroll
        for (int ni = 0; ni < 4; ni++)
#pragma unroll
            for (int r = 0; r < 4; r++) f.acc[mi][ni][r] = 0.f;

    // per-thread loader coordinates (4 chunks each side)
    const int lrow = tid >> 3;          // +32*j
    const int lk4  = tid & 7;

    float4 ra[4], rb[4];
#pragma unroll
    for (int j = 0; j < 4; j++) {
        const float* ap = aRow[j];
        ra[j] = ap ? *(const float4*)(ap + lk4 * 4) : make_float4(0.f,0.f,0.f,0.f);
        rb[j] = *(const float4*)(bRow[j] + lk4 * 4);
    }

    for (int kt = 0; kt < Kdim; kt += 32) {
        // store staged tile (with tf32 rounding)
#pragma unroll
        for (int j = 0; j < 4; j++) {
            int row = lrow + j * 32;
            unsigned* da = &As[swz(row, lk4)];
            da[0] = f2tf(ra[j].x); da[1] = f2tf(ra[j].y);
            da[2] = f2tf(ra[j].z); da[3] = f2tf(ra[j].w);
            unsigned* db = &Bs[swz(row, lk4)];
            db[0] = f2tf(rb[j].x); db[1] = f2tf(rb[j].y);
            db[2] = f2tf(rb[j].z); db[3] = f2tf(rb[j].w);
        }
        __syncthreads();

        // prefetch next tile
        if (kt + 32 < Kdim) {
#pragma unroll
            for (int j = 0; j < 4; j++) {
                const float* ap = aRow[j];
                ra[j] = ap ? *(const float4*)(ap + kt + 32 + lk4 * 4)
                           : make_float4(0.f,0.f,0.f,0.f);
                rb[j] = *(const float4*)(bRow[j] + kt + 32 + lk4 * 4);
            }
        }

        // compute 4 k8-steps
#pragma unroll
        for (int kk4 = 0; kk4 < 8; kk4 += 2) {
            unsigned a[4][4], b[4][2];
#pragma unroll
            for (int mi = 0; mi < 4; mi++) {
                int r0 = wm + mi * 16 + g;
                int base0 = ((kk4 ^ g) << 2) + t;
                int base1 = (((kk4 + 1) ^ g) << 2) + t;
                a[mi][0] = As[r0 * 32 + base0];
                a[mi][1] = As[(r0 + 8) * 32 + base0];
                a[mi][2] = As[r0 * 32 + base1];
                a[mi][3] = As[(r0 + 8) * 32 + base1];
            }
#pragma unroll
            for (int ni = 0; ni < 4; ni++) {
                int c0 = wn + ni * 8 + g;
                b[ni][0] = Bs[c0 * 32 + ((kk4 ^ (c0 & 7)) << 2) + t];
                b[ni][1] = Bs[c0 * 32 + (((kk4 + 1) ^ (c0 & 7)) << 2) + t];
            }
#pragma unroll
            for (int mi = 0; mi < 4; mi++)
#pragma unroll
                for (int ni = 0; ni < 4; ni++)
                    mma_tf32(f.acc[mi][ni], a[mi], b[ni]);
        }
        __syncthreads();
    }
}

// ---------------- GEMM1: g_h = tf32(gelu(x[tok] @ w1^T + b1)) ------------
__global__ void __launch_bounds__(256)
gemm1_kernel(const float* __restrict__ x,
             const float* __restrict__ w1,
             const float* __restrict__ b1) {
    const int e   = blockIdx.z;
    const int cnt = g_counts[e];
    const int m0  = blockIdx.y * 128;
    if (m0 >= cnt) return;
    const int n0  = blockIdx.x * 128;
    const int off = g_offsets[e];

    __shared__ unsigned As[128 * 32];
    __shared__ unsigned Bs[128 * 32];

    const int tid  = threadIdx.x;
    const int lrow = tid >> 3;
    const float* w1e = w1 + (size_t)e * HDIM * CDIM;

    const float* aRow[4];
    const float* bRow[4];
#pragma unroll
    for (int j = 0; j < 4; j++) {
        int gm = m0 + lrow + j * 32;
        aRow[j] = (gm < cnt) ? (x + (size_t)g_tokens[e * NTOK + gm] * CDIM) : (const float*)0;
        bRow[j] = w1e + (size_t)(n0 + lrow + j * 32) * CDIM;
    }

    Frag f;
    gemm_core(aRow, bRow, CDIM, As, Bs, f);

    const int lane = tid & 31, wid = tid >> 5;
    const int wm = (wid & 1) * 64, wn = (wid >> 1) * 32;
    const int g = lane >> 2, t = lane & 3;
#pragma unroll
    for (int mi = 0; mi < 4; mi++) {
        int r0 = m0 + wm + mi * 16 + g;
#pragma unroll
        for (int ni = 0; ni < 4; ni++) {
            int col = n0 + wn + ni * 8 + t * 2;
            float bv0 = b1[e * HDIM + col];
            float bv1 = b1[e * HDIM + col + 1];
            if (r0 < cnt) {
                float* h = g_h + (size_t)(off + r0) * HDIM + col;
                h[0] = __uint_as_float(f2tf(new_gelu(f.acc[mi][ni][0] + bv0)));
                h[1] = __uint_as_float(f2tf(new_gelu(f.acc[mi][ni][1] + bv1)));
            }
            if (r0 + 8 < cnt) {
                float* h = g_h + (size_t)(off + r0 + 8) * HDIM + col;
                h[0] = __uint_as_float(f2tf(new_gelu(f.acc[mi][ni][2] + bv0)));
                h[1] = __uint_as_float(f2tf(new_gelu(f.acc[mi][ni][3] + bv1)));
            }
        }
    }
}

// ---------------- GEMM2: out += gate * (h @ w2^T + b2) -------------------
__global__ void __launch_bounds__(256)
gemm2_kernel(const float* __restrict__ w2,
             const float* __restrict__ b2,
             float* __restrict__ out) {
    const int e   = blockIdx.z;
    const int cnt = g_counts[e];
    const int m0  = blockIdx.y * 128;
    if (m0 >= cnt) return;
    const int n0  = blockIdx.x * 128;
    const int off = g_offsets[e];

    __shared__ unsigned As[128 * 32];
    __shared__ unsigned Bs[128 * 32];

    const int tid  = threadIdx.x;
    const int lrow = tid >> 3;
    const float* w2e = w2 + (size_t)e * CDIM * HDIM;

    const float* aRow[4];
    const float* bRow[4];
#pragma unroll
    for (int j = 0; j < 4; j++) {
        int gm = m0 + lrow + j * 32;
        aRow[j] = (gm < cnt) ? (g_h + (size_t)(off + gm) * HDIM) : (const float*)0;
        bRow[j] = w2e + (size_t)(n0 + lrow + j * 32) * HDIM;
    }

    Frag f;
    gemm_core(aRow, bRow, HDIM, As, Bs, f);

    const int lane = tid & 31, wid = tid >> 5;
    const int wm = (wid & 1) * 64, wn = (wid >> 1) * 32;
    const int g = lane >> 2, t = lane & 3;
#pragma unroll
    for (int mi = 0; mi < 4; mi++) {
        int r0 = m0 + wm + mi * 16 + g;
#pragma unroll
        for (int half = 0; half < 2; half++) {
            int gm = r0 + half * 8;
            if (gm >= cnt) continue;
            int token  = g_tokens[e * NTOK + gm];
            float gate = g_gate[e * NTOK + gm];
            float* orow = out + (size_t)token * CDIM;
#pragma unroll
            for (int ni = 0; ni < 4; ni++) {
                int col = n0 + wn + ni * 8 + t * 2;
                float v0 = f.acc[mi][ni][half * 2 + 0] + b2[e * CDIM + col];
                float v1 = f.acc[mi][ni][half * 2 + 1] + b2[e * CDIM + col + 1];
                atomicAdd(&orow[col], gate * v0);
                atomicAdd(&orow[col + 1], gate * v1);
            }
        }
    }
}

// ---------------- launch ----------------
extern "C" void kernel_launch(void* const* d_in, const int* in_sizes, int n_in,
                              void* d_out, int out_size) {
    const float* x  = (const float*)d_in[0];
    const float* rw = (const float*)d_in[1];
    const float* w1 = (const float*)d_in[2];
    const float* b1 = (const float*)d_in[3];
    const float* w2 = (const float*)d_in[4];
    const float* b2 = (const float*)d_in[5];
    float* out = (float*)d_out;

    cudaMemsetAsync(out, 0, (size_t)out_size * sizeof(float), 0);
    init_kernel<<<1, 32>>>();
    router_kernel<<<(NTOK * 32 + 255) / 256, 256>>>(x, rw);
    offsets_kernel<<<1, 32>>>();

    dim3 g1(HDIM / 128, NTOK / 128, NEXP);
    gemm1_kernel<<<g1, 256>>>(x, w1, b1);

    dim3 g2(CDIM / 128, NTOK / 128, NEXP);
    gemm2_kernel<<<g2, 256>>>(w2, b2, out);
}

// round 3
// speedup vs baseline: 4.0379x; 1.5330x over previous
#include <cuda_runtime.h>
#include <math.h>

#define NTOK 8192
#define CDIM 1024
#define HDIM 4096
#define NEXP 8
#define NSLOT (2*NTOK)
#define STAGES 3
#define SZF 8192   // floats per pipeline stage (A 128x32 + B 128x32)

// ---------------- device scratch (static, allocation-free) ----------------
__device__ int   g_counts[NEXP];
__device__ int   g_offsets[NEXP];
__device__ int   g_tokens[NEXP * NTOK];
__device__ float g_gate[NEXP * NTOK];
__device__ float g_h[(size_t)NSLOT * HDIM];            // tf32-rounded activations
__device__ float g_w1t[(size_t)NEXP * HDIM * CDIM];    // tf32-rounded weights
__device__ float g_w2t[(size_t)NEXP * CDIM * HDIM];
__device__ float g_xt[(size_t)NTOK * CDIM];            // tf32-rounded x

// ---------------- helpers ----------------
__device__ __forceinline__ float new_gelu(float v) {
    const float c = 0.7978845608028654f;
    float u = c * (v + 0.044715f * v * v * v);
    return 0.5f * v * (1.0f + tanhf(u));
}
__device__ __forceinline__ unsigned f2tf(float f) {
    unsigned u;
    asm("cvt.rna.tf32.f32 %0, %1;" : "=r"(u) : "f"(f));
    return u;
}
__device__ __forceinline__ void mma_tf32(float* c, const unsigned* a, const unsigned* b) {
    asm volatile(
        "mma.sync.aligned.m16n8k8.row.col.f32.tf32.tf32.f32 "
        "{%0,%1,%2,%3}, {%4,%5,%6,%7}, {%8,%9}, {%0,%1,%2,%3};"
        : "+f"(c[0]), "+f"(c[1]), "+f"(c[2]), "+f"(c[3])
        : "r"(a[0]), "r"(a[1]), "r"(a[2]), "r"(a[3]), "r"(b[0]), "r"(b[1]));
}
__device__ __forceinline__ int swz(int row, int k4) {
    return row * 32 + ((k4 ^ (row & 7)) << 2);
}
__device__ __forceinline__ void cp16(float* dst_smem, const float* src, int src_size) {
    unsigned sa = (unsigned)__cvta_generic_to_shared(dst_smem);
    asm volatile("cp.async.cg.shared.global [%0], [%1], 16, %2;"
                 :: "r"(sa), "l"(src), "r"(src_size));
}
__device__ __forceinline__ void cp_commit() {
    asm volatile("cp.async.commit_group;" ::: "memory");
}
template <int N>
__device__ __forceinline__ void cp_wait() {
    asm volatile("cp.async.wait_group %0;" :: "n"(N) : "memory");
}

// ---------------- kernel 0: reset counters ----------------
__global__ void init_kernel() {
    if (threadIdx.x < NEXP) g_counts[threadIdx.x] = 0;
}

// ---------------- prep: tf32-round weights and x into scratch -------------
__global__ void prep_kernel(const float* __restrict__ w1,
                            const float* __restrict__ w2,
                            const float* __restrict__ x) {
    const size_t N1 = (size_t)NEXP * HDIM * CDIM / 4;       // 8388608
    const size_t N2 = N1 * 2;                               // 16777216
    const size_t N3 = N2 + (size_t)NTOK * CDIM / 4;         // 18874368
    size_t i = (size_t)blockIdx.x * 256 + threadIdx.x;
    if (i >= N3) return;
    float4 v; float4* o;
    if (i < N1)      { v = ((const float4*)w1)[i];      o = (float4*)g_w1t + i; }
    else if (i < N2) { v = ((const float4*)w2)[i - N1]; o = (float4*)g_w2t + (i - N1); }
    else             { v = ((const float4*)x)[i - N2];  o = (float4*)g_xt + (i - N2); }
    v.x = __uint_as_float(f2tf(v.x));
    v.y = __uint_as_float(f2tf(v.y));
    v.z = __uint_as_float(f2tf(v.z));
    v.w = __uint_as_float(f2tf(v.w));
    *o = v;
}

// ---------------- kernel 1: router (one warp per token) ----------------
__global__ void router_kernel(const float* __restrict__ x,
                              const float* __restrict__ rw) {
    int warp = (blockIdx.x * blockDim.x + threadIdx.x) >> 5;
    int lane = threadIdx.x & 31;
    if (warp >= NTOK) return;
    const float* xr = x + (size_t)warp * CDIM;

    float acc[NEXP];
#pragma unroll
    for (int e = 0; e < NEXP; e++) acc[e] = 0.f;
    for (int c = lane; c < CDIM; c += 32) {
        float xv = xr[c];
#pragma unroll
        for (int e = 0; e < NEXP; e++)
            acc[e] = fmaf(xv, rw[e * CDIM + c], acc[e]);
    }
#pragma unroll
    for (int off = 16; off > 0; off >>= 1)
#pragma unroll
        for (int e = 0; e < NEXP; e++)
            acc[e] += __shfl_xor_sync(0xffffffffu, acc[e], off);

    if (lane == 0) {
        float mx = acc[0];
#pragma unroll
        for (int e = 1; e < NEXP; e++) mx = fmaxf(mx, acc[e]);
        float p[NEXP], s = 0.f;
#pragma unroll
        for (int e = 0; e < NEXP; e++) { p[e] = expf(acc[e] - mx); s += p[e]; }
        float inv = 1.f / s;
#pragma unroll
        for (int e = 0; e < NEXP; e++) p[e] *= inv;

        int i0 = 0;
#pragma unroll
        for (int e = 1; e < NEXP; e++) if (p[e] > p[i0]) i0 = e;
        int i1 = (i0 == 0) ? 1 : 0;
#pragma unroll
        for (int e = 0; e < NEXP; e++)
            if (e != i0 && p[e] > p[i1]) i1 = e;

        float denom = p[i0] + p[i1] + 1e-8f;
        int pos0 = atomicAdd(&g_counts[i0], 1);
        g_tokens[i0 * NTOK + pos0] = warp;
        g_gate[i0 * NTOK + pos0]   = p[i0] / denom;
        int pos1 = atomicAdd(&g_counts[i1], 1);
        g_tokens[i1 * NTOK + pos1] = warp;
        g_gate[i1 * NTOK + pos1]   = p[i1] / denom;
    }
}

// ---------------- kernel 2: exclusive prefix ----------------
__global__ void offsets_kernel() {
    if (threadIdx.x == 0) {
        int s = 0;
        for (int e = 0; e < NEXP; e++) { g_offsets[e] = s; s += g_counts[e]; }
    }
}

// =====================================================================
// TF32 tensor-core GEMMs: BM=128 BN=128 BK=32, 8 warps, warp tile 64x32
// cp.async 3-stage pipeline; operands pre-rounded to tf32 in global.
// =====================================================================

__device__ __forceinline__ void compute_stage(
    const unsigned* __restrict__ As, const unsigned* __restrict__ Bs,
    int wm, int wn, int g, int t, float acc[4][4][4])
{
#pragma unroll
    for (int kk4 = 0; kk4 < 8; kk4 += 2) {
        unsigned a[4][4], b[4][2];
        int base0 = ((kk4 ^ g) << 2) + t;
        int base1 = (((kk4 + 1) ^ g) << 2) + t;
#pragma unroll
        for (int mi = 0; mi < 4; mi++) {
            int r0 = wm + mi * 16 + g;
            a[mi][0] = As[r0 * 32 + base0];
            a[mi][1] = As[(r0 + 8) * 32 + base0];
            a[mi][2] = As[r0 * 32 + base1];
            a[mi][3] = As[(r0 + 8) * 32 + base1];
        }
#pragma unroll
        for (int ni = 0; ni < 4; ni++) {
            int c0 = wn + ni * 8 + g;              // c0 & 7 == g
            b[ni][0] = Bs[c0 * 32 + base0];
            b[ni][1] = Bs[c0 * 32 + base1];
        }
#pragma unroll
        for (int mi = 0; mi < 4; mi++)
#pragma unroll
            for (int ni = 0; ni < 4; ni++)
                mma_tf32(acc[mi][ni], a[mi], b[ni]);
    }
}

// gemm body shared by both kernels via macro-free duplication (A gather differs)
#define GEMM_PIPELINE(Kdim)                                                   \
    const int tid  = threadIdx.x;                                             \
    const int lane = tid & 31;                                                \
    const int wid  = tid >> 5;                                                \
    const int wm   = (wid & 1) * 64;                                          \
    const int wn   = (wid >> 1) * 32;                                         \
    const int g    = lane >> 2;                                               \
    const int t    = lane & 3;                                                \
    const int lrow = tid >> 3;                                                \
    const int lk4  = tid & 7;                                                 \
    float acc[4][4][4];                                                       \
    _Pragma("unroll")                                                         \
    for (int mi = 0; mi < 4; mi++)                                            \
        _Pragma("unroll")                                                     \
        for (int ni = 0; ni < 4; ni++)                                        \
            _Pragma("unroll")                                                 \
            for (int r = 0; r < 4; r++) acc[mi][ni][r] = 0.f;                 \
    extern __shared__ float smem[];                                           \
    auto issue = [&](int stage, int kt) {                                     \
        float* As_s = smem + stage * SZF;                                     \
        float* Bs_s = As_s + 4096;                                            \
        _Pragma("unroll")                                                     \
        for (int j = 0; j < 4; j++) {                                         \
            int row = lrow + j * 32;                                          \
            const float* sa = aRow[j] ? aRow[j] + kt + lk4 * 4 : bRow[0];     \
            cp16(As_s + swz(row, lk4), sa, aRow[j] ? 16 : 0);                 \
            cp16(Bs_s + swz(row, lk4), bRow[j] + kt + lk4 * 4, 16);           \
        }                                                                     \
    };                                                                        \
    const int KT = (Kdim) / 32;                                               \
    issue(0, 0); cp_commit();                                                 \
    issue(1, 32); cp_commit();                                                \
    int cs = 0, ns = 2;                                                       \
    for (int i = 0; i < KT; i++) {                                            \
        cp_wait<STAGES - 2>();                                                \
        __syncthreads();                                                      \
        int ktn = (i + STAGES - 1) * 32;                                      \
        if (ktn < (Kdim)) issue(ns, ktn);                                     \
        cp_commit();                                                          \
        compute_stage((const unsigned*)(smem + cs * SZF),                     \
                      (const unsigned*)(smem + cs * SZF + 4096),              \
                      wm, wn, g, t, acc);                                     \
        if (++cs == STAGES) cs = 0;                                           \
        if (++ns == STAGES) ns = 0;                                           \
    }

// ---------------- GEMM1: g_h = tf32(gelu(xt[tok] @ w1t^T + b1)) -----------
__global__ void __launch_bounds__(256, 2)
gemm1_kernel(const float* __restrict__ b1) {
    const int e   = blockIdx.z;
    const int cnt = g_counts[e];
    const int m0  = blockIdx.y * 128;
    if (m0 >= cnt) return;
    const int n0  = blockIdx.x * 128;
    const int off = g_offsets[e];
    const float* w1e = g_w1t + (size_t)e * HDIM * CDIM;

    const float* aRow[4];
    const float* bRow[4];
    {
        const int lr = threadIdx.x >> 3;
#pragma unroll
        for (int j = 0; j < 4; j++) {
            int gm = m0 + lr + j * 32;
            aRow[j] = (gm < cnt) ? (g_xt + (size_t)g_tokens[e * NTOK + gm] * CDIM)
                                 : (const float*)0;
            bRow[j] = w1e + (size_t)(n0 + lr + j * 32) * CDIM;
        }
    }

    GEMM_PIPELINE(CDIM)

#pragma unroll
    for (int mi = 0; mi < 4; mi++) {
        int r0 = m0 + wm + mi * 16 + g;
#pragma unroll
        for (int ni = 0; ni < 4; ni++) {
            int col = n0 + wn + ni * 8 + t * 2;
            float bv0 = b1[e * HDIM + col];
            float bv1 = b1[e * HDIM + col + 1];
            if (r0 < cnt) {
                float* h = g_h + (size_t)(off + r0) * HDIM + col;
                h[0] = __uint_as_float(f2tf(new_gelu(acc[mi][ni][0] + bv0)));
                h[1] = __uint_as_float(f2tf(new_gelu(acc[mi][ni][1] + bv1)));
            }
            if (r0 + 8 < cnt) {
                float* h = g_h + (size_t)(off + r0 + 8) * HDIM + col;
                h[0] = __uint_as_float(f2tf(new_gelu(acc[mi][ni][2] + bv0)));
                h[1] = __uint_as_float(f2tf(new_gelu(acc[mi][ni][3] + bv1)));
            }
        }
    }
}

// ---------------- GEMM2: out += gate * (h @ w2t^T + b2) -------------------
__global__ void __launch_bounds__(256, 2)
gemm2_kernel(const float* __restrict__ b2, float* __restrict__ out) {
    const int e   = blockIdx.z;
    const int cnt = g_counts[e];
    const int m0  = blockIdx.y * 128;
    if (m0 >= cnt) return;
    const int n0  = blockIdx.x * 128;
    const int off = g_offsets[e];
    const float* w2e = g_w2t + (size_t)e * CDIM * HDIM;

    const float* aRow[4];
    const float* bRow[4];
    {
        const int lr = threadIdx.x >> 3;
#pragma unroll
        for (int j = 0; j < 4; j++) {
            int gm = m0 + lr + j * 32;
            aRow[j] = (gm < cnt) ? (g_h + (size_t)(off + gm) * HDIM) : (const float*)0;
            bRow[j] = w2e + (size_t)(n0 + lr + j * 32) * HDIM;
        }
    }

    GEMM_PIPELINE(HDIM)

#pragma unroll
    for (int mi = 0; mi < 4; mi++) {
        int r0 = m0 + wm + mi * 16 + g;
#pragma unroll
        for (int half = 0; half < 2; half++) {
            int gm = r0 + half * 8;
            if (gm >= cnt) continue;
            int token  = g_tokens[e * NTOK + gm];
            float gate = g_gate[e * NTOK + gm];
            float* orow = out + (size_t)token * CDIM;
#pragma unroll
            for (int ni = 0; ni < 4; ni++) {
                int col = n0 + wn + ni * 8 + t * 2;
                float v0 = acc[mi][ni][half * 2 + 0] + b2[e * CDIM + col];
                float v1 = acc[mi][ni][half * 2 + 1] + b2[e * CDIM + col + 1];
                atomicAdd(&orow[col], gate * v0);
                atomicAdd(&orow[col + 1], gate * v1);
            }
        }
    }
}

// ---------------- launch ----------------
extern "C" void kernel_launch(void* const* d_in, const int* in_sizes, int n_in,
                              void* d_out, int out_size) {
    const float* x  = (const float*)d_in[0];
    const float* rw = (const float*)d_in[1];
    const float* w1 = (const float*)d_in[2];
    const float* b1 = (const float*)d_in[3];
    const float* w2 = (const float*)d_in[4];
    const float* b2 = (const float*)d_in[5];
    float* out = (float*)d_out;

    const int smem_bytes = STAGES * SZF * 4;  // 96 KB
    cudaFuncSetAttribute(gemm1_kernel, cudaFuncAttributeMaxDynamicSharedMemorySize, smem_bytes);
    cudaFuncSetAttribute(gemm2_kernel, cudaFuncAttributeMaxDynamicSharedMemorySize, smem_bytes);

    cudaMemsetAsync(out, 0, (size_t)out_size * sizeof(float), 0);
    init_kernel<<<1, 32>>>();

    const size_t nprep = ((size_t)NEXP * HDIM * CDIM * 2 + (size_t)NTOK * CDIM) / 4;
    prep_kernel<<<(unsigned)((nprep + 255) / 256), 256>>>(w1, w2, x);

    router_kernel<<<(NTOK * 32 + 255) / 256, 256>>>(x, rw);
    offsets_kernel<<<1, 32>>>();

    dim3 g1(HDIM / 128, NTOK / 128, NEXP);
    gemm1_kernel<<<g1, 256, smem_bytes>>>(b1);

    dim3 g2(CDIM / 128, NTOK / 128, NEXP);
    gemm2_kernel<<<g2, 256, smem_bytes>>>(b2, out);
}